// round 12
// baseline (speedup 1.0000x reference)
#include <cuda_runtime.h>
#include <cuda_bf16.h>
#include <cstdint>

#define HDIM 512
#define ROWS 64          // rows per CTA
#define NT   512         // 16 warps
#define HBS  520         // bf16 h row stride (elements) -> conflict-free ldmatrix A
#define KCH  32          // K per chunk
#define NCH  16          // chunks per GEMM
#define WKP  40          // padded k-extent per W chunk row (80 B) -> conflict-free ldmatrix B
#define CHW  (512*WKP)        // elements per W chunk
#define CHBYTES (CHW*2)       // 40960 B per W chunk
#define NBUF 3

__device__ float g_sf[2][4][HDIM];
// bf16 W2/W3 (f1,f2), chunked [mat][chunk][n][WKP]
__device__ __align__(16) __nv_bfloat16 g_wb[4][NCH*CHW];

// ---------------- helpers ----------------
__device__ __forceinline__ uint32_t smem_u32(const void* p){
    uint32_t a;
    asm("{ .reg .u64 t; cvta.to.shared.u64 t, %1; cvt.u32.u64 %0, t; }" : "=r"(a) : "l"(p));
    return a;
}
__device__ __forceinline__ void mbar_wait(uint32_t mbar, uint32_t parity){
    asm volatile(
        "{\n\t.reg .pred P;\n\t"
        "LAB%=:\n\t"
        "mbarrier.try_wait.parity.acquire.cta.shared::cta.b64 P, [%0], %1, 0x989680;\n\t"
        "@!P bra LAB%=;\n\t}"
        :: "r"(mbar), "r"(parity) : "memory");
}
#define MBAR_INIT(a, c)   asm volatile("mbarrier.init.shared.b64 [%0], %1;" :: "r"(a), "r"((uint32_t)(c)) : "memory")
#define MBAR_INVAL(a)     asm volatile("mbarrier.inval.shared.b64 [%0];" :: "r"(a) : "memory")
#define MBAR_EXPECT(a, b) asm volatile("mbarrier.arrive.expect_tx.shared.b64 _, [%0], %1;" :: "r"(a), "r"((uint32_t)(b)) : "memory")
#define MBAR_ARRIVE(a)    asm volatile("mbarrier.arrive.shared.b64 _, [%0];" :: "r"(a) : "memory")
#define BULK_G2S(dst, src, mbar) \
    asm volatile("cp.async.bulk.shared::cluster.global.mbarrier::complete_tx::bytes [%0], [%1], %2, [%3];" \
        :: "r"(dst), "l"(src), "r"((uint32_t)CHBYTES), "r"(mbar) : "memory")
#define LDMX4(r, addr) \
    asm volatile("ldmatrix.sync.aligned.m8n8.x4.shared.b16 {%0,%1,%2,%3}, [%4];" \
        : "=r"((r)[0]), "=r"((r)[1]), "=r"((r)[2]), "=r"((r)[3]) : "r"(addr))
#define MMA_BF16(d, a, b0, b1) \
    asm volatile("mma.sync.aligned.m16n8k16.row.col.f32.bf16.bf16.f32 " \
        "{%0,%1,%2,%3}, {%4,%5,%6,%7}, {%8,%9}, {%0,%1,%2,%3};" \
        : "+f"((d)[0]), "+f"((d)[1]), "+f"((d)[2]), "+f"((d)[3]) \
        : "r"((a)[0]), "r"((a)[1]), "r"((a)[2]), "r"((a)[3]), "r"(b0), "r"(b1))

// ---------------- prep: pack W2/W3 as bf16 chunks, padded rows ----------------
__global__ void prep_w(const float* __restrict__ W2a, const float* __restrict__ W3a,
                       const float* __restrict__ W2b, const float* __restrict__ W3b){
    int mat = blockIdx.y;
    const float* W = mat==0 ? W2a : mat==1 ? W3a : mat==2 ? W2b : W3b;
    int c = blockIdx.x;                    // chunk
    int kk = threadIdx.x & 31;
    int ns = threadIdx.x >> 5;             // 0..15
    for (int n = ns; n < 512; n += 16){
        float v = W[n*HDIM + c*KCH + kk];
        g_wb[mat][(c*512 + n)*WKP + kk] = __float2bfloat16_rn(v);
    }
}

// sf[f][b][:] = tanh(code[b] @ cond_w^T + cond_b)
__global__ void sf_kernel(const float* __restrict__ code,
                          const float* __restrict__ cw1, const float* __restrict__ cb1,
                          const float* __restrict__ cw2, const float* __restrict__ cb2){
    int b = blockIdx.x, f = blockIdx.y, t = threadIdx.x;
    const float* cw = f ? cw2 : cw1;
    const float* cb = f ? cb2 : cb1;
    const float4* c4 = reinterpret_cast<const float4*>(code + b*HDIM);
    const float4* w4 = reinterpret_cast<const float4*>(cw + t*HDIM);
    float s = 0.f;
    #pragma unroll 4
    for (int i = 0; i < HDIM/4; i++){
        float4 a = c4[i], w = w4[i];
        s = fmaf(a.x, w.x, fmaf(a.y, w.y, fmaf(a.z, w.z, fmaf(a.w, w.w, s))));
    }
    g_sf[f][b][t] = tanhf(s + cb[t]);
}

__global__ __launch_bounds__(NT, 1)
void deform_kernel(const float* __restrict__ x_in, float* __restrict__ x_out,
    const float* __restrict__ W1a, const float* __restrict__ b1a,
    const float* __restrict__ b2a, const float* __restrict__ b3a,
    const float* __restrict__ W4a, const float* __restrict__ b4a,
    const float* __restrict__ W1b, const float* __restrict__ b1b,
    const float* __restrict__ b2b, const float* __restrict__ b3b,
    const float* __restrict__ W4b, const float* __restrict__ b4b)
{
    extern __shared__ char dsm[];
    uintptr_t pa = (reinterpret_cast<uintptr_t>(dsm) + 1023) & ~(uintptr_t)1023;
    char* hb  = reinterpret_cast<char*>(pa);            // 64 x 520 bf16 = 66560 B
    char* wc  = hb + ROWS*HBS*2;                        // 3 x 40960 B
    float* msc = reinterpret_cast<float*>(wc + NBUF*CHBYTES);
    float* sfs  = msc;
    float* b1s  = msc + 512;
    float* b2s  = msc + 1024;
    float* b3s  = msc + 1536;
    float* w1xs = msc + 2048;
    float* w1ys = msc + 2560;
    float* w1zs = msc + 3072;
    float* w4s  = msc + 3584;   // 3*512

    uint32_t* hb2 = reinterpret_cast<uint32_t*>(hb);    // bf16-pair view, stride HBS/2

    __shared__ __align__(8) unsigned long long mbarF_s[NBUF], mbarE_s[NBUF];
    __shared__ float p0[ROWS][3], pe[ROWS][3], ksum[ROWS][3], kcur[ROWS][3];

    const int tid = threadIdx.x;
    const int wid = tid >> 5, lane = tid & 31;
    const int g = lane >> 2, tig = lane & 3;
    const int rbase = (wid & 1) * 32;
    const int colbase = (wid >> 1) * 64;
    const int phase = wid & 3;             // B-tile rotation phase per warp
    const int base = blockIdx.x * ROWS;
    const int b = base >> 12;

    const uint32_t hb_u32 = smem_u32(hb);
    const uint32_t wc_u32 = smem_u32(wc);
    const uint32_t mbarF = smem_u32(&mbarF_s[0]);
    const uint32_t mbarE = smem_u32(&mbarE_s[0]);

    // ldmatrix lane-address components
    const uint32_t a_lrow = (uint32_t)(lane & 15);
    const uint32_t a_koff = (lane & 16) ? 8u : 0u;
    const uint32_t b_lrow = (uint32_t)((lane & 7) + ((lane & 16) ? 8 : 0));
    const uint32_t b_koff = (lane & 8) ? 8u : 0u;

    if (tid == 0){
        #pragma unroll
        for (int j = 0; j < NBUF; ++j){
            MBAR_INIT(mbarF + j*8, 1);
            MBAR_INIT(mbarE + j*8, 16);   // one arrive per warp
        }
    }
    if (tid < ROWS*3){
        int r = tid/3, j = tid - r*3;
        float v = x_in[(base + r)*3 + j];
        p0[r][j] = v; pe[r][j] = v;
    }
    __syncthreads();

    uint32_t gb = 0;          // global chunk counter (buffer rotation)
    uint32_t cful = 0;        // consumer full-parity bits per buffer
    uint32_t pemp = 0x7;      // producer empty-parity bits

    const float dt = 0.05f;   // TIME / N_STEPS

    for (int f = 0; f < 2; ++f){
        const float* W1 = f ? W1b : W1a;
        const float* B1 = f ? b1b : b1a;
        const float* B2 = f ? b2b : b2a;
        const float* B3 = f ? b3b : b3a;
        const float* W4 = f ? W4b : W4a;
        const float* B4 = f ? b4b : b4a;
        const __nv_bfloat16* Wc2 = g_wb[f*2 + 0];
        const __nv_bfloat16* Wc3 = g_wb[f*2 + 1];

        __syncthreads();
        {
            int c = tid;
            sfs[c]  = g_sf[f][b][c];
            b1s[c]  = B1[c]; b2s[c] = B2[c]; b3s[c] = B3[c];
            w1xs[c] = W1[c*3+0]; w1ys[c] = W1[c*3+1]; w1zs[c] = W1[c*3+2];
            w4s[c]        = W4[c];
            w4s[512 + c]  = W4[512 + c];
            w4s[1024 + c] = W4[1024 + c];
        }
        __syncthreads();

        auto issue = [&](int t){
            uint32_t j = (gb + (uint32_t)t) % NBUF;
            mbar_wait(mbarE + j*8, (pemp >> j) & 1u);
            pemp ^= (1u << j);
            MBAR_EXPECT(mbarF + j*8, CHBYTES);
            const __nv_bfloat16* src = (t < NCH) ? (Wc2 + (size_t)t*CHW)
                                                 : (Wc3 + (size_t)(t - NCH)*CHW);
            BULK_G2S(wc_u32 + j*CHBYTES, src, mbarF + j*8);
        };

        for (int step = 0; step < 4; ++step){
            for (int s = 0; s < 4; ++s){
                if (tid == 0){ issue(0); issue(1); }

                // ---- stage 1: h = bf16(relu(pe @ W1^T + b1) * sf); warp w -> rows 4w..4w+3
                #pragma unroll
                for (int cc = 0; cc < 4; ++cc){
                    int c4 = cc*128 + lane*4;
                    float4 wx = *reinterpret_cast<const float4*>(&w1xs[c4]);
                    float4 wy = *reinterpret_cast<const float4*>(&w1ys[c4]);
                    float4 wz = *reinterpret_cast<const float4*>(&w1zs[c4]);
                    float4 bb = *reinterpret_cast<const float4*>(&b1s[c4]);
                    float4 sf4 = *reinterpret_cast<const float4*>(&sfs[c4]);
                    #pragma unroll
                    for (int rr = 0; rr < 4; ++rr){
                        int r = wid*4 + rr;
                        float px = pe[r][0], py = pe[r][1], pz = pe[r][2];
                        float ox = fmaxf(fmaf(px, wx.x, fmaf(py, wy.x, fmaf(pz, wz.x, bb.x))), 0.f) * sf4.x;
                        float oy = fmaxf(fmaf(px, wx.y, fmaf(py, wy.y, fmaf(pz, wz.y, bb.y))), 0.f) * sf4.y;
                        float oz = fmaxf(fmaf(px, wx.z, fmaf(py, wy.z, fmaf(pz, wz.z, bb.z))), 0.f) * sf4.z;
                        float ow = fmaxf(fmaf(px, wx.w, fmaf(py, wy.w, fmaf(pz, wz.w, bb.w))), 0.f) * sf4.w;
                        __nv_bfloat162 pA = __floats2bfloat162_rn(ox, oy);
                        __nv_bfloat162 pB = __floats2bfloat162_rn(oz, ow);
                        uint2 pk = make_uint2(*reinterpret_cast<uint32_t*>(&pA),
                                              *reinterpret_cast<uint32_t*>(&pB));
                        *reinterpret_cast<uint2*>(&hb2[r*(HBS/2) + (c4 >> 1)]) = pk;
                    }
                }
                __syncthreads();   // h published before A-frag reads

                // ---- two residual GEMMs, staggered + software-pipelined chunk stream
                #pragma unroll 1
                for (int gg = 0; gg < 2; ++gg){
                    const float* bias_s = gg ? b3s : b2s;
                    const int lo = gg*NCH;

                    float acc[2][8][4];
                    #pragma unroll
                    for (int m = 0; m < 2; ++m)
                        #pragma unroll
                        for (int j = 0; j < 8; ++j)
                            #pragma unroll
                            for (int q = 0; q < 4; ++q) acc[m][j][q] = 0.f;

                    #pragma unroll 1
                    for (int c = 0; c < NCH; ++c){
                        const int t = lo + c;
                        if (tid == 0 && t + 2 < 2*NCH) issue(t + 2);

                        uint32_t j = (gb + (uint32_t)t) % NBUF;
                        mbar_wait(mbarF + j*8, (cful >> j) & 1u);
                        cful ^= (1u << j);
                        const uint32_t wcu = wc_u32 + j*CHBYTES;

                        // A frags for s2=0 now; s2=1 loaded mid-stream
                        uint32_t Afr[2][2][4];
                        #pragma unroll
                        for (int m = 0; m < 2; ++m){
                            uint32_t addr = hb_u32 +
                                (((uint32_t)(rbase + 16*m) + a_lrow)*HBS + (uint32_t)(c*KCH) + a_koff)*2u;
                            LDMX4(Afr[m][0], addr);
                        }

                        // staggered + pipelined B stream: tiles (s2, jt=(j+phase)&3)
                        uint32_t Bc[4], Bn[4];
                        {
                            uint32_t addr0 = wcu +
                                (((uint32_t)(colbase + 16*phase) + b_lrow)*WKP + b_koff)*2u;
                            LDMX4(Bc, addr0);
                        }
                        #pragma unroll
                        for (int s2 = 0; s2 < 2; ++s2){
                            #pragma unroll
                            for (int jj = 0; jj < 4; ++jj){
                                const int jt = (jj + phase) & 3;
                                // prefetch next B tile
                                if (!(s2 == 1 && jj == 3)){
                                    const int ns2 = (jj == 3) ? 1 : s2;
                                    const int njt = (jj == 3) ? phase : ((jj + 1 + phase) & 3);
                                    uint32_t addr = wcu +
                                        (((uint32_t)(colbase + 16*njt) + b_lrow)*WKP + (uint32_t)(ns2*16) + b_koff)*2u;
                                    LDMX4(Bn, addr);
                                }
                                MMA_BF16(acc[0][2*jt],   Afr[0][s2], Bc[0], Bc[1]);
                                MMA_BF16(acc[0][2*jt+1], Afr[0][s2], Bc[2], Bc[3]);
                                MMA_BF16(acc[1][2*jt],   Afr[1][s2], Bc[0], Bc[1]);
                                MMA_BF16(acc[1][2*jt+1], Afr[1][s2], Bc[2], Bc[3]);
                                // A frags for s2=1 loaded during first MMA batch
                                if (s2 == 0 && jj == 0){
                                    #pragma unroll
                                    for (int m = 0; m < 2; ++m){
                                        uint32_t addr = hb_u32 +
                                            (((uint32_t)(rbase + 16*m) + a_lrow)*HBS + (uint32_t)(c*KCH + 16) + a_koff)*2u;
                                        LDMX4(Afr[m][1], addr);
                                    }
                                }
                                Bc[0] = Bn[0]; Bc[1] = Bn[1]; Bc[2] = Bn[2]; Bc[3] = Bn[3];
                            }
                        }
                        if (lane == 0) MBAR_ARRIVE(mbarE + j*8);
                    }
                    __syncthreads();   // all warps consumed all chunks before h rewritten

                    // epilogue: h = bf16(relu(acc + bias) + h), in place (thread-owned cells)
                    #pragma unroll
                    for (int m = 0; m < 2; ++m){
                        int r = rbase + 16*m + g;
                        #pragma unroll
                        for (int j = 0; j < 8; ++j){
                            int cc = colbase + 8*j + 2*tig;
                            float bi0 = bias_s[cc], bi1 = bias_s[cc+1];
                            #pragma unroll
                            for (int hh = 0; hh < 2; ++hh){
                                uint32_t* hp = &hb2[(r + 8*hh)*(HBS/2) + (cc >> 1)];
                                __nv_bfloat162 old = *reinterpret_cast<__nv_bfloat162*>(hp);
                                float nx = fmaxf(acc[m][j][2*hh]   + bi0, 0.f) + __bfloat162float(old.x);
                                float ny = fmaxf(acc[m][j][2*hh+1] + bi1, 0.f) + __bfloat162float(old.y);
                                __nv_bfloat162 nv = __floats2bfloat162_rn(nx, ny);
                                *hp = *reinterpret_cast<uint32_t*>(&nv);
                            }
                        }
                    }
                    __syncthreads();   // h published before next consumer
                }
                gb += 2*NCH;

                // ---- stage 4: kcur = tanh(h @ W4^T + b4); warp w -> rows 4w..4w+3
                {
                    float a[4][3];
                    #pragma unroll
                    for (int rr = 0; rr < 4; ++rr){ a[rr][0]=0.f; a[rr][1]=0.f; a[rr][2]=0.f; }
                    #pragma unroll 2
                    for (int i = 0; i < 8; ++i){
                        int idx = lane + i*32;          // bf16-pair index
                        float w00 = w4s[2*idx],        w01 = w4s[2*idx+1];
                        float w10 = w4s[512 + 2*idx],  w11 = w4s[512 + 2*idx+1];
                        float w20 = w4s[1024 + 2*idx], w21 = w4s[1024 + 2*idx+1];
                        #pragma unroll
                        for (int rr = 0; rr < 4; ++rr){
                            uint32_t pv = hb2[(wid*4 + rr)*(HBS/2) + idx];
                            __nv_bfloat162 hv = *reinterpret_cast<__nv_bfloat162*>(&pv);
                            float hx = __bfloat162float(hv.x), hy = __bfloat162float(hv.y);
                            a[rr][0] = fmaf(hx, w00, fmaf(hy, w01, a[rr][0]));
                            a[rr][1] = fmaf(hx, w10, fmaf(hy, w11, a[rr][1]));
                            a[rr][2] = fmaf(hx, w20, fmaf(hy, w21, a[rr][2]));
                        }
                    }
                    #pragma unroll
                    for (int rr = 0; rr < 4; ++rr){
                        #pragma unroll
                        for (int j = 0; j < 3; ++j){
                            float v = a[rr][j];
                            #pragma unroll
                            for (int off = 16; off > 0; off >>= 1)
                                v += __shfl_xor_sync(0xffffffffu, v, off);
                            if (lane == 0) kcur[wid*4 + rr][j] = tanhf(v + B4[j]);
                        }
                    }
                }
                __syncthreads();

                // ---- RK4 state update
                if (tid < ROWS*3){
                    int r = tid/3, j = tid - r*3;
                    float k = kcur[r][j];
                    if (s == 0){ ksum[r][j] = k;            pe[r][j] = fmaf(0.5f*dt, k, p0[r][j]); }
                    else if (s == 1){ ksum[r][j] += 2.f*k;  pe[r][j] = fmaf(0.5f*dt, k, p0[r][j]); }
                    else if (s == 2){ ksum[r][j] += 2.f*k;  pe[r][j] = fmaf(dt, k, p0[r][j]); }
                    else { float p = fmaf(dt/6.f, ksum[r][j] + k, p0[r][j]); p0[r][j] = p; pe[r][j] = p; }
                }
                __syncthreads();
            }
        }
    }

    if (tid < ROWS*3){
        int r = tid/3, j = tid - r*3;
        x_out[(base + r)*3 + j] = p0[r][j];
    }
    __syncthreads();
    if (tid == 0){
        #pragma unroll
        for (int j = 0; j < NBUF; ++j){ MBAR_INVAL(mbarF + j*8); MBAR_INVAL(mbarE + j*8); }
    }
}

extern "C" void kernel_launch(void* const* d_in, const int* in_sizes, int n_in,
                              void* d_out, int out_size)
{
    const float* code   = (const float*)d_in[0];
    const float* x      = (const float*)d_in[1];
    const float* f1_l1w = (const float*)d_in[2];
    const float* f1_l1b = (const float*)d_in[3];
    const float* f1_l2w = (const float*)d_in[4];
    const float* f1_l2b = (const float*)d_in[5];
    const float* f1_l3w = (const float*)d_in[6];
    const float* f1_l3b = (const float*)d_in[7];
    const float* f1_l4w = (const float*)d_in[8];
    const float* f1_l4b = (const float*)d_in[9];
    const float* f1_cw  = (const float*)d_in[10];
    const float* f1_cb  = (const float*)d_in[11];
    const float* f2_l1w = (const float*)d_in[12];
    const float* f2_l1b = (const float*)d_in[13];
    const float* f2_l2w = (const float*)d_in[14];
    const float* f2_l2b = (const float*)d_in[15];
    const float* f2_l3w = (const float*)d_in[16];
    const float* f2_l3b = (const float*)d_in[17];
    const float* f2_l4w = (const float*)d_in[18];
    const float* f2_l4b = (const float*)d_in[19];
    const float* f2_cw  = (const float*)d_in[20];
    const float* f2_cb  = (const float*)d_in[21];
    float* out = (float*)d_out;

    const int smem_bytes = 1024 + ROWS*HBS*2 + NBUF*CHBYTES + 5120*4;   // ~211 KB
    cudaFuncSetAttribute(deform_kernel, cudaFuncAttributeMaxDynamicSharedMemorySize, smem_bytes);

    prep_w<<<dim3(NCH, 4), NT>>>(f1_l2w, f1_l3w, f2_l2w, f2_l3w);
    sf_kernel<<<dim3(4, 2), HDIM>>>(code, f1_cw, f1_cb, f2_cw, f2_cb);

    const int n_blocks = (4 * 4096) / ROWS;  // 256
    deform_kernel<<<n_blocks, NT, smem_bytes>>>(
        x, out,
        f1_l1w, f1_l1b, f1_l2b, f1_l3b, f1_l4w, f1_l4b,
        f2_l1w, f2_l1b, f2_l2b, f2_l3b, f2_l4w, f2_l4b);
}

// round 13
// speedup vs baseline: 7.4262x; 7.4262x over previous
#include <cuda_runtime.h>
#include <cuda_bf16.h>
#include <cstdint>

#define HDIM 512
#define ROWS 64          // rows per CTA
#define NT   512         // 16 warps
#define HBS  520         // bf16 h row stride (elements) -> conflict-free ldmatrix A
#define KCH  32          // K per chunk
#define NCH  16          // chunks per GEMM
#define WKP  40          // padded k-extent per W chunk row (80 B) -> conflict-free ldmatrix B
#define CHW  (512*WKP)        // elements per W chunk
#define CHBYTES (CHW*2)       // 40960 B per W chunk
#define NBUF 3

__device__ float g_sf[2][4][HDIM];
// bf16 W2/W3 (f1,f2), chunked [mat][chunk][n][WKP]
__device__ __align__(16) __nv_bfloat16 g_wb[4][NCH*CHW];

// ---------------- helpers ----------------
__device__ __forceinline__ uint32_t smem_u32(const void* p){
    uint32_t a;
    asm("{ .reg .u64 t; cvta.to.shared.u64 t, %1; cvt.u32.u64 %0, t; }" : "=r"(a) : "l"(p));
    return a;
}
__device__ __forceinline__ void mbar_wait(uint32_t mbar, uint32_t parity){
    asm volatile(
        "{\n\t.reg .pred P;\n\t"
        "LAB%=:\n\t"
        "mbarrier.try_wait.parity.acquire.cta.shared::cta.b64 P, [%0], %1, 0x989680;\n\t"
        "@!P bra LAB%=;\n\t}"
        :: "r"(mbar), "r"(parity) : "memory");
}
#define MBAR_INIT(a, c)   asm volatile("mbarrier.init.shared.b64 [%0], %1;" :: "r"(a), "r"((uint32_t)(c)) : "memory")
#define MBAR_INVAL(a)     asm volatile("mbarrier.inval.shared.b64 [%0];" :: "r"(a) : "memory")
#define MBAR_EXPECT(a, b) asm volatile("mbarrier.arrive.expect_tx.shared.b64 _, [%0], %1;" :: "r"(a), "r"((uint32_t)(b)) : "memory")
#define MBAR_ARRIVE(a)    asm volatile("mbarrier.arrive.shared.b64 _, [%0];" :: "r"(a) : "memory")
#define BULK_G2S(dst, src, mbar) \
    asm volatile("cp.async.bulk.shared::cluster.global.mbarrier::complete_tx::bytes [%0], [%1], %2, [%3];" \
        :: "r"(dst), "l"(src), "r"((uint32_t)CHBYTES), "r"(mbar) : "memory")
#define LDMX4(r, addr) \
    asm volatile("ldmatrix.sync.aligned.m8n8.x4.shared.b16 {%0,%1,%2,%3}, [%4];" \
        : "=r"((r)[0]), "=r"((r)[1]), "=r"((r)[2]), "=r"((r)[3]) : "r"(addr))
#define MMA_BF16(d, a, b0, b1) \
    asm volatile("mma.sync.aligned.m16n8k16.row.col.f32.bf16.bf16.f32 " \
        "{%0,%1,%2,%3}, {%4,%5,%6,%7}, {%8,%9}, {%0,%1,%2,%3};" \
        : "+f"((d)[0]), "+f"((d)[1]), "+f"((d)[2]), "+f"((d)[3]) \
        : "r"((a)[0]), "r"((a)[1]), "r"((a)[2]), "r"((a)[3]), "r"(b0), "r"(b1))

// ---------------- prep: pack W2/W3 as bf16 chunks, padded rows ----------------
__global__ void prep_w(const float* __restrict__ W2a, const float* __restrict__ W3a,
                       const float* __restrict__ W2b, const float* __restrict__ W3b){
    int mat = blockIdx.y;
    const float* W = mat==0 ? W2a : mat==1 ? W3a : mat==2 ? W2b : W3b;
    int c = blockIdx.x;                    // chunk
    int kk = threadIdx.x & 31;
    int ns = threadIdx.x >> 5;             // 0..15
    for (int n = ns; n < 512; n += 16){
        float v = W[n*HDIM + c*KCH + kk];
        g_wb[mat][(c*512 + n)*WKP + kk] = __float2bfloat16_rn(v);
    }
}

// sf[f][b][:] = tanh(code[b] @ cond_w^T + cond_b)
__global__ void sf_kernel(const float* __restrict__ code,
                          const float* __restrict__ cw1, const float* __restrict__ cb1,
                          const float* __restrict__ cw2, const float* __restrict__ cb2){
    int b = blockIdx.x, f = blockIdx.y, t = threadIdx.x;
    const float* cw = f ? cw2 : cw1;
    const float* cb = f ? cb2 : cb1;
    const float4* c4 = reinterpret_cast<const float4*>(code + b*HDIM);
    const float4* w4 = reinterpret_cast<const float4*>(cw + t*HDIM);
    float s = 0.f;
    #pragma unroll 4
    for (int i = 0; i < HDIM/4; i++){
        float4 a = c4[i], w = w4[i];
        s = fmaf(a.x, w.x, fmaf(a.y, w.y, fmaf(a.z, w.z, fmaf(a.w, w.w, s))));
    }
    g_sf[f][b][t] = tanhf(s + cb[t]);
}

// chunk MMA body with COMPILE-TIME phase rotation (no runtime-indexed regs!)
template<int PH>
__device__ __forceinline__ void chunk_mma(float (&acc)[2][8][4],
    uint32_t hb_u32, uint32_t wcu, int c, int rbase, int colbase,
    uint32_t a_lrow, uint32_t a_koff, uint32_t b_lrow, uint32_t b_koff)
{
    uint32_t Afr[2][2][4];
    #pragma unroll
    for (int m = 0; m < 2; ++m)
        #pragma unroll
        for (int s2 = 0; s2 < 2; ++s2){
            uint32_t addr = hb_u32 +
                (((uint32_t)(rbase + 16*m) + a_lrow)*HBS + (uint32_t)(c*KCH + s2*16) + a_koff)*2u;
            LDMX4(Afr[m][s2], addr);
        }
    #pragma unroll
    for (int s2 = 0; s2 < 2; ++s2){
        #pragma unroll
        for (int jj = 0; jj < 4; ++jj){
            const int jt = (jj + PH) & 3;   // compile-time constant
            uint32_t Bf[4];
            uint32_t addr = wcu +
                (((uint32_t)(colbase + 16*jt) + b_lrow)*WKP + (uint32_t)(s2*16) + b_koff)*2u;
            LDMX4(Bf, addr);
            MMA_BF16(acc[0][2*jt],   Afr[0][s2], Bf[0], Bf[1]);
            MMA_BF16(acc[0][2*jt+1], Afr[0][s2], Bf[2], Bf[3]);
            MMA_BF16(acc[1][2*jt],   Afr[1][s2], Bf[0], Bf[1]);
            MMA_BF16(acc[1][2*jt+1], Afr[1][s2], Bf[2], Bf[3]);
        }
    }
}

__global__ __launch_bounds__(NT, 1)
void deform_kernel(const float* __restrict__ x_in, float* __restrict__ x_out,
    const float* __restrict__ W1a, const float* __restrict__ b1a,
    const float* __restrict__ b2a, const float* __restrict__ b3a,
    const float* __restrict__ W4a, const float* __restrict__ b4a,
    const float* __restrict__ W1b, const float* __restrict__ b1b,
    const float* __restrict__ b2b, const float* __restrict__ b3b,
    const float* __restrict__ W4b, const float* __restrict__ b4b)
{
    extern __shared__ char dsm[];
    uintptr_t pa = (reinterpret_cast<uintptr_t>(dsm) + 1023) & ~(uintptr_t)1023;
    char* hb  = reinterpret_cast<char*>(pa);            // 64 x 520 bf16 = 66560 B
    char* wc  = hb + ROWS*HBS*2;                        // 3 x 40960 B
    float* msc = reinterpret_cast<float*>(wc + NBUF*CHBYTES);
    float* sfs  = msc;
    float* b1s  = msc + 512;
    float* b2s  = msc + 1024;
    float* b3s  = msc + 1536;
    float* w1xs = msc + 2048;
    float* w1ys = msc + 2560;
    float* w1zs = msc + 3072;
    float* w4s  = msc + 3584;   // 3*512

    uint32_t* hb2 = reinterpret_cast<uint32_t*>(hb);    // bf16-pair view, stride HBS/2

    __shared__ __align__(8) unsigned long long mbarF_s[NBUF], mbarE_s[NBUF];
    __shared__ float p0[ROWS][3], pe[ROWS][3], ksum[ROWS][3], kcur[ROWS][3];
    __shared__ float kpart[ROWS][8][3];   // fused stage4 partials

    const int tid = threadIdx.x;
    const int wid = tid >> 5, lane = tid & 31;
    const int g = lane >> 2, tig = lane & 3;
    const int rbase = (wid & 1) * 32;
    const int colbase = (wid >> 1) * 64;
    const int cw = wid >> 1;
    const int phase = (wid >> 2) & 3;   // warps on the SAME SMSP (wid&3) get distinct phases
    const int base = blockIdx.x * ROWS;
    const int b = base >> 12;

    const uint32_t hb_u32 = smem_u32(hb);
    const uint32_t wc_u32 = smem_u32(wc);
    const uint32_t mbarF = smem_u32(&mbarF_s[0]);
    const uint32_t mbarE = smem_u32(&mbarE_s[0]);

    // ldmatrix lane-address components
    const uint32_t a_lrow = (uint32_t)(lane & 15);
    const uint32_t a_koff = (lane & 16) ? 8u : 0u;
    const uint32_t b_lrow = (uint32_t)((lane & 7) + ((lane & 16) ? 8 : 0));
    const uint32_t b_koff = (lane & 8) ? 8u : 0u;

    if (tid == 0){
        #pragma unroll
        for (int j = 0; j < NBUF; ++j){
            MBAR_INIT(mbarF + j*8, 1);
            MBAR_INIT(mbarE + j*8, 16);   // one arrive per warp
        }
    }
    if (tid < ROWS*3){
        int r = tid/3, j = tid - r*3;
        float v = x_in[(base + r)*3 + j];
        p0[r][j] = v; pe[r][j] = v;
    }
    __syncthreads();

    uint32_t gb = 0;          // global chunk counter (buffer rotation)
    uint32_t cful = 0;        // consumer full-parity bits per buffer
    uint32_t pemp = 0x7;      // producer empty-parity bits

    const float dt = 0.05f;   // TIME / N_STEPS

    for (int f = 0; f < 2; ++f){
        const float* W1 = f ? W1b : W1a;
        const float* B1 = f ? b1b : b1a;
        const float* B2 = f ? b2b : b2a;
        const float* B3 = f ? b3b : b3a;
        const float* W4 = f ? W4b : W4a;
        const float* B4 = f ? b4b : b4a;
        const __nv_bfloat16* Wc2 = g_wb[f*2 + 0];
        const __nv_bfloat16* Wc3 = g_wb[f*2 + 1];

        __syncthreads();
        {
            int c = tid;
            sfs[c]  = g_sf[f][b][c];
            b1s[c]  = B1[c]; b2s[c] = B2[c]; b3s[c] = B3[c];
            w1xs[c] = W1[c*3+0]; w1ys[c] = W1[c*3+1]; w1zs[c] = W1[c*3+2];
            w4s[c]        = W4[c];
            w4s[512 + c]  = W4[512 + c];
            w4s[1024 + c] = W4[1024 + c];
        }
        __syncthreads();

        auto issue = [&](int t){
            uint32_t j = (gb + (uint32_t)t) % NBUF;
            mbar_wait(mbarE + j*8, (pemp >> j) & 1u);
            pemp ^= (1u << j);
            MBAR_EXPECT(mbarF + j*8, CHBYTES);
            const __nv_bfloat16* src = (t < NCH) ? (Wc2 + (size_t)t*CHW)
                                                 : (Wc3 + (size_t)(t - NCH)*CHW);
            BULK_G2S(wc_u32 + j*CHBYTES, src, mbarF + j*8);
        };

        for (int step = 0; step < 4; ++step){
            for (int s = 0; s < 4; ++s){
                if (tid == 0){ issue(0); issue(1); }

                // ---- stage 1: h = bf16(relu(pe @ W1^T + b1) * sf); warp w -> rows 4w..4w+3
                #pragma unroll
                for (int cc = 0; cc < 4; ++cc){
                    int c4 = cc*128 + lane*4;
                    float4 wx = *reinterpret_cast<const float4*>(&w1xs[c4]);
                    float4 wy = *reinterpret_cast<const float4*>(&w1ys[c4]);
                    float4 wz = *reinterpret_cast<const float4*>(&w1zs[c4]);
                    float4 bb = *reinterpret_cast<const float4*>(&b1s[c4]);
                    float4 sf4 = *reinterpret_cast<const float4*>(&sfs[c4]);
                    #pragma unroll
                    for (int rr = 0; rr < 4; ++rr){
                        int r = wid*4 + rr;
                        float px = pe[r][0], py = pe[r][1], pz = pe[r][2];
                        float ox = fmaxf(fmaf(px, wx.x, fmaf(py, wy.x, fmaf(pz, wz.x, bb.x))), 0.f) * sf4.x;
                        float oy = fmaxf(fmaf(px, wx.y, fmaf(py, wy.y, fmaf(pz, wz.y, bb.y))), 0.f) * sf4.y;
                        float oz = fmaxf(fmaf(px, wx.z, fmaf(py, wy.z, fmaf(pz, wz.z, bb.z))), 0.f) * sf4.z;
                        float ow = fmaxf(fmaf(px, wx.w, fmaf(py, wy.w, fmaf(pz, wz.w, bb.w))), 0.f) * sf4.w;
                        __nv_bfloat162 pA = __floats2bfloat162_rn(ox, oy);
                        __nv_bfloat162 pB = __floats2bfloat162_rn(oz, ow);
                        uint2 pk = make_uint2(*reinterpret_cast<uint32_t*>(&pA),
                                              *reinterpret_cast<uint32_t*>(&pB));
                        *reinterpret_cast<uint2*>(&hb2[r*(HBS/2) + (c4 >> 1)]) = pk;
                    }
                }
                __syncthreads();   // h published before A-frag reads

                // ================= GEMM 1 (W2): h = relu(h@W2^T + b2) + h =================
                {
                    float acc[2][8][4];
                    #pragma unroll
                    for (int m = 0; m < 2; ++m)
                        #pragma unroll
                        for (int j = 0; j < 8; ++j)
                            #pragma unroll
                            for (int q = 0; q < 4; ++q) acc[m][j][q] = 0.f;

                    #pragma unroll 1
                    for (int c = 0; c < NCH; ++c){
                        if (tid == 0 && c + 2 < 2*NCH) issue(c + 2);
                        uint32_t j = (gb + (uint32_t)c) % NBUF;
                        mbar_wait(mbarF + j*8, (cful >> j) & 1u);
                        cful ^= (1u << j);
                        const uint32_t wcu = wc_u32 + j*CHBYTES;
                        switch (phase){
                            case 0: chunk_mma<0>(acc, hb_u32, wcu, c, rbase, colbase, a_lrow, a_koff, b_lrow, b_koff); break;
                            case 1: chunk_mma<1>(acc, hb_u32, wcu, c, rbase, colbase, a_lrow, a_koff, b_lrow, b_koff); break;
                            case 2: chunk_mma<2>(acc, hb_u32, wcu, c, rbase, colbase, a_lrow, a_koff, b_lrow, b_koff); break;
                            default: chunk_mma<3>(acc, hb_u32, wcu, c, rbase, colbase, a_lrow, a_koff, b_lrow, b_koff); break;
                        }
                        if (lane == 0) MBAR_ARRIVE(mbarE + j*8);
                    }
                    __syncthreads();   // all warps done reading hb before rewrite

                    #pragma unroll
                    for (int m = 0; m < 2; ++m){
                        int r = rbase + 16*m + g;
                        #pragma unroll
                        for (int j = 0; j < 8; ++j){
                            int cc = colbase + 8*j + 2*tig;
                            float bi0 = b2s[cc], bi1 = b2s[cc+1];
                            #pragma unroll
                            for (int hh = 0; hh < 2; ++hh){
                                uint32_t* hp = &hb2[(r + 8*hh)*(HBS/2) + (cc >> 1)];
                                __nv_bfloat162 old = *reinterpret_cast<__nv_bfloat162*>(hp);
                                float nx = fmaxf(acc[m][j][2*hh]   + bi0, 0.f) + __bfloat162float(old.x);
                                float ny = fmaxf(acc[m][j][2*hh+1] + bi1, 0.f) + __bfloat162float(old.y);
                                __nv_bfloat162 nv = __floats2bfloat162_rn(nx, ny);
                                *hp = *reinterpret_cast<uint32_t*>(&nv);
                            }
                        }
                    }
                    __syncthreads();   // h published for GEMM 2
                }

                // ===== GEMM 2 (W3) + fused stage 4: kcur = tanh((relu(h@W3+b3)+h) @ W4^T + b4) =====
                {
                    float acc[2][8][4];
                    #pragma unroll
                    for (int m = 0; m < 2; ++m)
                        #pragma unroll
                        for (int j = 0; j < 8; ++j)
                            #pragma unroll
                            for (int q = 0; q < 4; ++q) acc[m][j][q] = 0.f;

                    #pragma unroll 1
                    for (int c = 0; c < NCH; ++c){
                        const int t = NCH + c;
                        if (tid == 0 && t + 2 < 2*NCH) issue(t + 2);
                        uint32_t j = (gb + (uint32_t)t) % NBUF;
                        mbar_wait(mbarF + j*8, (cful >> j) & 1u);
                        cful ^= (1u << j);
                        const uint32_t wcu = wc_u32 + j*CHBYTES;
                        switch (phase){
                            case 0: chunk_mma<0>(acc, hb_u32, wcu, c, rbase, colbase, a_lrow, a_koff, b_lrow, b_koff); break;
                            case 1: chunk_mma<1>(acc, hb_u32, wcu, c, rbase, colbase, a_lrow, a_koff, b_lrow, b_koff); break;
                            case 2: chunk_mma<2>(acc, hb_u32, wcu, c, rbase, colbase, a_lrow, a_koff, b_lrow, b_koff); break;
                            default: chunk_mma<3>(acc, hb_u32, wcu, c, rbase, colbase, a_lrow, a_koff, b_lrow, b_koff); break;
                        }
                        if (lane == 0) MBAR_ARRIVE(mbarE + j*8);
                    }
                    // no hb rewrite in this epilogue -> no barrier needed here

                    // fused epilogue: h3 in fp32 regs, partial W4 dots
                    float kp[2][2][3];
                    #pragma unroll
                    for (int m = 0; m < 2; ++m)
                        #pragma unroll
                        for (int hh = 0; hh < 2; ++hh){
                            kp[m][hh][0] = 0.f; kp[m][hh][1] = 0.f; kp[m][hh][2] = 0.f;
                        }
                    #pragma unroll
                    for (int m = 0; m < 2; ++m){
                        int r = rbase + 16*m + g;
                        #pragma unroll
                        for (int j = 0; j < 8; ++j){
                            int cc = colbase + 8*j + 2*tig;
                            float bi0 = b3s[cc], bi1 = b3s[cc+1];
                            float w40 = w4s[cc],        w41 = w4s[cc+1];
                            float w50 = w4s[512+cc],    w51 = w4s[512+cc+1];
                            float w60 = w4s[1024+cc],   w61 = w4s[1024+cc+1];
                            #pragma unroll
                            for (int hh = 0; hh < 2; ++hh){
                                uint32_t pv = hb2[(r + 8*hh)*(HBS/2) + (cc >> 1)];
                                __nv_bfloat162 old = *reinterpret_cast<__nv_bfloat162*>(&pv);
                                float nx = fmaxf(acc[m][j][2*hh]   + bi0, 0.f) + __bfloat162float(old.x);
                                float ny = fmaxf(acc[m][j][2*hh+1] + bi1, 0.f) + __bfloat162float(old.y);
                                kp[m][hh][0] = fmaf(nx, w40, fmaf(ny, w41, kp[m][hh][0]));
                                kp[m][hh][1] = fmaf(nx, w50, fmaf(ny, w51, kp[m][hh][1]));
                                kp[m][hh][2] = fmaf(nx, w60, fmaf(ny, w61, kp[m][hh][2]));
                            }
                        }
                    }
                    // reduce across tig (lanes 0..3 within each g)
                    #pragma unroll
                    for (int m = 0; m < 2; ++m)
                        #pragma unroll
                        for (int hh = 0; hh < 2; ++hh)
                            #pragma unroll
                            for (int d = 0; d < 3; ++d){
                                float v = kp[m][hh][d];
                                v += __shfl_xor_sync(0xffffffffu, v, 1);
                                v += __shfl_xor_sync(0xffffffffu, v, 2);
                                if (tig == 0) kpart[rbase + 16*m + g + 8*hh][cw][d] = v;
                            }
                    __syncthreads();
                    if (tid < ROWS*3){
                        int r = tid/3, d = tid - r*3;
                        float v = kpart[r][0][d];
                        #pragma unroll
                        for (int i = 1; i < 8; ++i) v += kpart[r][i][d];
                        kcur[r][d] = tanhf(v + B4[d]);
                    }
                    __syncthreads();
                }
                gb += 2*NCH;

                // ---- RK4 state update
                if (tid < ROWS*3){
                    int r = tid/3, j = tid - r*3;
                    float k = kcur[r][j];
                    if (s == 0){ ksum[r][j] = k;            pe[r][j] = fmaf(0.5f*dt, k, p0[r][j]); }
                    else if (s == 1){ ksum[r][j] += 2.f*k;  pe[r][j] = fmaf(0.5f*dt, k, p0[r][j]); }
                    else if (s == 2){ ksum[r][j] += 2.f*k;  pe[r][j] = fmaf(dt, k, p0[r][j]); }
                    else { float p = fmaf(dt/6.f, ksum[r][j] + k, p0[r][j]); p0[r][j] = p; pe[r][j] = p; }
                }
                __syncthreads();
            }
        }
    }

    if (tid < ROWS*3){
        int r = tid/3, j = tid - r*3;
        x_out[(base + r)*3 + j] = p0[r][j];
    }
    __syncthreads();
    if (tid == 0){
        #pragma unroll
        for (int j = 0; j < NBUF; ++j){ MBAR_INVAL(mbarF + j*8); MBAR_INVAL(mbarE + j*8); }
    }
}

extern "C" void kernel_launch(void* const* d_in, const int* in_sizes, int n_in,
                              void* d_out, int out_size)
{
    const float* code   = (const float*)d_in[0];
    const float* x      = (const float*)d_in[1];
    const float* f1_l1w = (const float*)d_in[2];
    const float* f1_l1b = (const float*)d_in[3];
    const float* f1_l2w = (const float*)d_in[4];
    const float* f1_l2b = (const float*)d_in[5];
    const float* f1_l3w = (const float*)d_in[6];
    const float* f1_l3b = (const float*)d_in[7];
    const float* f1_l4w = (const float*)d_in[8];
    const float* f1_l4b = (const float*)d_in[9];
    const float* f1_cw  = (const float*)d_in[10];
    const float* f1_cb  = (const float*)d_in[11];
    const float* f2_l1w = (const float*)d_in[12];
    const float* f2_l1b = (const float*)d_in[13];
    const float* f2_l2w = (const float*)d_in[14];
    const float* f2_l2b = (const float*)d_in[15];
    const float* f2_l3w = (const float*)d_in[16];
    const float* f2_l3b = (const float*)d_in[17];
    const float* f2_l4w = (const float*)d_in[18];
    const float* f2_l4b = (const float*)d_in[19];
    const float* f2_cw  = (const float*)d_in[20];
    const float* f2_cb  = (const float*)d_in[21];
    float* out = (float*)d_out;

    const int smem_bytes = 1024 + ROWS*HBS*2 + NBUF*CHBYTES + 5120*4;   // ~211 KB dynamic
    cudaFuncSetAttribute(deform_kernel, cudaFuncAttributeMaxDynamicSharedMemorySize, smem_bytes);

    prep_w<<<dim3(NCH, 4), NT>>>(f1_l2w, f1_l3w, f2_l2w, f2_l3w);
    sf_kernel<<<dim3(4, 2), HDIM>>>(code, f1_cw, f1_cb, f2_cw, f2_cb);

    const int n_blocks = (4 * 4096) / ROWS;  // 256
    deform_kernel<<<n_blocks, NT, smem_bytes>>>(
        x, out,
        f1_l1w, f1_l1b, f1_l2b, f1_l3b, f1_l4w, f1_l4b,
        f2_l1w, f2_l1b, f2_l2b, f2_l3b, f2_l4w, f2_l4b);
}

// round 14
// speedup vs baseline: 7.5086x; 1.0111x over previous
#include <cuda_runtime.h>
#include <cuda_bf16.h>
#include <cstdint>

#define HDIM 512
#define ROWS 64          // rows per CTA
#define NT   512         // 16 warps
#define HBS  520         // bf16 h row stride (elements) -> conflict-free ldmatrix A
#define KCH  32          // K per chunk
#define NCH  16          // chunks per GEMM
#define CHELEM (512*KCH)      // elements per W chunk (16384)
#define CHBYTES (CHELEM*2)    // 32768 B per W chunk (unpadded, swizzled)
#define NBUF 3

__device__ float g_sf[2][4][HDIM];
// bf16 W2/W3 (f1,f2), chunked + XOR-swizzled: see prep_w
__device__ __align__(16) __nv_bfloat16 g_wb[4][NCH*CHELEM];

// ---------------- helpers ----------------
__device__ __forceinline__ uint32_t smem_u32(const void* p){
    uint32_t a;
    asm("{ .reg .u64 t; cvta.to.shared.u64 t, %1; cvt.u32.u64 %0, t; }" : "=r"(a) : "l"(p));
    return a;
}
__device__ __forceinline__ void mbar_wait(uint32_t mbar, uint32_t parity){
    asm volatile(
        "{\n\t.reg .pred P;\n\t"
        "LAB%=:\n\t"
        "mbarrier.try_wait.parity.acquire.cta.shared::cta.b64 P, [%0], %1, 0x989680;\n\t"
        "@!P bra LAB%=;\n\t}"
        :: "r"(mbar), "r"(parity) : "memory");
}
#define MBAR_INIT(a, c)   asm volatile("mbarrier.init.shared.b64 [%0], %1;" :: "r"(a), "r"((uint32_t)(c)) : "memory")
#define MBAR_INVAL(a)     asm volatile("mbarrier.inval.shared.b64 [%0];" :: "r"(a) : "memory")
#define MBAR_EXPECT(a, b) asm volatile("mbarrier.arrive.expect_tx.shared.b64 _, [%0], %1;" :: "r"(a), "r"((uint32_t)(b)) : "memory")
#define MBAR_ARRIVE(a)    asm volatile("mbarrier.arrive.shared.b64 _, [%0];" :: "r"(a) : "memory")
#define BULK_G2S(dst, src, mbar) \
    asm volatile("cp.async.bulk.shared::cluster.global.mbarrier::complete_tx::bytes [%0], [%1], %2, [%3];" \
        :: "r"(dst), "l"(src), "r"((uint32_t)CHBYTES), "r"(mbar) : "memory")
#define LDMX4(r, addr) \
    asm volatile("ldmatrix.sync.aligned.m8n8.x4.shared.b16 {%0,%1,%2,%3}, [%4];" \
        : "=r"((r)[0]), "=r"((r)[1]), "=r"((r)[2]), "=r"((r)[3]) : "r"(addr))
#define MMA_BF16(d, a, b0, b1) \
    asm volatile("mma.sync.aligned.m16n8k16.row.col.f32.bf16.bf16.f32 " \
        "{%0,%1,%2,%3}, {%4,%5,%6,%7}, {%8,%9}, {%0,%1,%2,%3};" \
        : "+f"((d)[0]), "+f"((d)[1]), "+f"((d)[2]), "+f"((d)[3]) \
        : "r"((a)[0]), "r"((a)[1]), "r"((a)[2]), "r"((a)[3]), "r"(b0), "r"(b1))

// ---------------- prep: pack W2/W3 as bf16 chunks, XOR-swizzled (no padding) ----------------
// element (n, kk) of chunk c  ->  16B unit  4n + ((kk>>3) ^ ((n>>1)&3)),  sub-offset (kk&7)
__global__ void prep_w(const float* __restrict__ W2a, const float* __restrict__ W3a,
                       const float* __restrict__ W2b, const float* __restrict__ W3b){
    int mat = blockIdx.y;
    const float* W = mat==0 ? W2a : mat==1 ? W3a : mat==2 ? W2b : W3b;
    int c = blockIdx.x;                    // chunk
    int kk = threadIdx.x & 31;
    int ns = threadIdx.x >> 5;             // 0..15
    for (int n = ns; n < 512; n += 16){
        float v = W[n*HDIM + c*KCH + kk];
        uint32_t unit = (uint32_t)(4*n) + (uint32_t)((kk >> 3) ^ ((n >> 1) & 3));
        uint32_t elem = unit*8u + (uint32_t)(kk & 7);
        g_wb[mat][(size_t)c*CHELEM + elem] = __float2bfloat16_rn(v);
    }
}

// sf[f][b][:] = tanh(code[b] @ cond_w^T + cond_b)
__global__ void sf_kernel(const float* __restrict__ code,
                          const float* __restrict__ cw1, const float* __restrict__ cb1,
                          const float* __restrict__ cw2, const float* __restrict__ cb2){
    int b = blockIdx.x, f = blockIdx.y, t = threadIdx.x;
    const float* cw = f ? cw2 : cw1;
    const float* cb = f ? cb2 : cb1;
    const float4* c4 = reinterpret_cast<const float4*>(code + b*HDIM);
    const float4* w4 = reinterpret_cast<const float4*>(cw + t*HDIM);
    float s = 0.f;
    #pragma unroll 4
    for (int i = 0; i < HDIM/4; i++){
        float4 a = c4[i], w = w4[i];
        s = fmaf(a.x, w.x, fmaf(a.y, w.y, fmaf(a.z, w.z, fmaf(a.w, w.w, s))));
    }
    g_sf[f][b][t] = tanhf(s + cb[t]);
}

// chunk MMA body with COMPILE-TIME phase rotation; B addresses use the XOR-swizzled layout
template<int PH>
__device__ __forceinline__ void chunk_mma(float (&acc)[2][8][4],
    uint32_t hb_u32, uint32_t wcu, int c, int rbase, int colbase,
    uint32_t a_lrow, uint32_t a_koff, uint32_t b_lrow, uint32_t bq)
{
    uint32_t Afr[2][2][4];
    #pragma unroll
    for (int m = 0; m < 2; ++m)
        #pragma unroll
        for (int s2 = 0; s2 < 2; ++s2){
            uint32_t addr = hb_u32 +
                (((uint32_t)(rbase + 16*m) + a_lrow)*HBS + (uint32_t)(c*KCH + s2*16) + a_koff)*2u;
            LDMX4(Afr[m][s2], addr);
        }
    #pragma unroll
    for (int s2 = 0; s2 < 2; ++s2){
        #pragma unroll
        for (int jj = 0; jj < 4; ++jj){
            const int jt = (jj + PH) & 3;   // compile-time constant
            uint32_t Bf[4];
            uint32_t n = (uint32_t)(colbase + 16*jt) + b_lrow;
            uint32_t q = 2u*(uint32_t)s2 + bq;
            uint32_t unit = (n << 2) + (q ^ ((n >> 1) & 3u));
            uint32_t addr = wcu + (unit << 4);
            LDMX4(Bf, addr);
            MMA_BF16(acc[0][2*jt],   Afr[0][s2], Bf[0], Bf[1]);
            MMA_BF16(acc[0][2*jt+1], Afr[0][s2], Bf[2], Bf[3]);
            MMA_BF16(acc[1][2*jt],   Afr[1][s2], Bf[0], Bf[1]);
            MMA_BF16(acc[1][2*jt+1], Afr[1][s2], Bf[2], Bf[3]);
        }
    }
}

__global__ __launch_bounds__(NT, 1)
void deform_kernel(const float* __restrict__ x_in, float* __restrict__ x_out,
    const float* __restrict__ W1a, const float* __restrict__ b1a,
    const float* __restrict__ b2a, const float* __restrict__ b3a,
    const float* __restrict__ W4a, const float* __restrict__ b4a,
    const float* __restrict__ W1b, const float* __restrict__ b1b,
    const float* __restrict__ b2b, const float* __restrict__ b3b,
    const float* __restrict__ W4b, const float* __restrict__ b4b)
{
    extern __shared__ char dsm[];
    uintptr_t pa = (reinterpret_cast<uintptr_t>(dsm) + 1023) & ~(uintptr_t)1023;
    char* hb  = reinterpret_cast<char*>(pa);            // 64 x 520 bf16 = 66560 B
    char* wc  = hb + ROWS*HBS*2;                        // 3 x 32768 B
    float* msc = reinterpret_cast<float*>(wc + NBUF*CHBYTES);
    float* sfs  = msc;
    float* b1s  = msc + 512;
    float* b2s  = msc + 1024;
    float* b3s  = msc + 1536;
    float* w1xs = msc + 2048;
    float* w1ys = msc + 2560;
    float* w1zs = msc + 3072;
    float* w4s  = msc + 3584;   // 3*512

    uint32_t* hb2 = reinterpret_cast<uint32_t*>(hb);    // bf16-pair view, stride HBS/2

    __shared__ __align__(8) unsigned long long mbarF_s[NBUF], mbarE_s[NBUF];
    __shared__ float p0[ROWS][3], pe[ROWS][3], ksum[ROWS][3], kcur[ROWS][3];
    __shared__ float kpart[ROWS][8][3];   // fused stage4 partials

    const int tid = threadIdx.x;
    const int wid = tid >> 5, lane = tid & 31;
    const int g = lane >> 2, tig = lane & 3;
    const int rbase = (wid & 1) * 32;
    const int colbase = (wid >> 1) * 64;
    const int cw = wid >> 1;
    const int phase = (wid >> 2) & 3;   // warps on the SAME SMSP (wid&3) get distinct phases
    const int base = blockIdx.x * ROWS;
    const int b = base >> 12;

    const uint32_t hb_u32 = smem_u32(hb);
    const uint32_t wc_u32 = smem_u32(wc);
    const uint32_t mbarF = smem_u32(&mbarF_s[0]);
    const uint32_t mbarE = smem_u32(&mbarE_s[0]);

    // ldmatrix lane-address components
    const uint32_t a_lrow = (uint32_t)(lane & 15);
    const uint32_t a_koff = (lane & 16) ? 8u : 0u;
    const uint32_t b_lrow = (uint32_t)((lane & 7) + ((lane & 16) ? 8 : 0));
    const uint32_t bq     = (lane & 8) ? 1u : 0u;       // k 16B-unit select within k-half

    if (tid == 0){
        #pragma unroll
        for (int j = 0; j < NBUF; ++j){
            MBAR_INIT(mbarF + j*8, 1);
            MBAR_INIT(mbarE + j*8, 16);   // one arrive per warp
        }
    }
    if (tid < ROWS*3){
        int r = tid/3, j = tid - r*3;
        float v = x_in[(base + r)*3 + j];
        p0[r][j] = v; pe[r][j] = v;
    }
    __syncthreads();

    uint32_t gb = 0;          // global chunk counter (buffer rotation)
    uint32_t cful = 0;        // consumer full-parity bits per buffer
    uint32_t pemp = 0x7;      // producer empty-parity bits

    const float dt = 0.05f;   // TIME / N_STEPS

    for (int f = 0; f < 2; ++f){
        const float* W1 = f ? W1b : W1a;
        const float* B1 = f ? b1b : b1a;
        const float* B2 = f ? b2b : b2a;
        const float* B3 = f ? b3b : b3a;
        const float* W4 = f ? W4b : W4a;
        const float* B4 = f ? b4b : b4a;
        const __nv_bfloat16* Wc2 = g_wb[f*2 + 0];
        const __nv_bfloat16* Wc3 = g_wb[f*2 + 1];

        __syncthreads();
        {
            int c = tid;
            sfs[c]  = g_sf[f][b][c];
            b1s[c]  = B1[c]; b2s[c] = B2[c]; b3s[c] = B3[c];
            w1xs[c] = W1[c*3+0]; w1ys[c] = W1[c*3+1]; w1zs[c] = W1[c*3+2];
            w4s[c]        = W4[c];
            w4s[512 + c]  = W4[512 + c];
            w4s[1024 + c] = W4[1024 + c];
        }
        __syncthreads();

        auto issue = [&](int t){
            uint32_t j = (gb + (uint32_t)t) % NBUF;
            mbar_wait(mbarE + j*8, (pemp >> j) & 1u);
            pemp ^= (1u << j);
            MBAR_EXPECT(mbarF + j*8, CHBYTES);
            const __nv_bfloat16* src = (t < NCH) ? (Wc2 + (size_t)t*CHELEM)
                                                 : (Wc3 + (size_t)(t - NCH)*CHELEM);
            BULK_G2S(wc_u32 + j*CHBYTES, src, mbarF + j*8);
        };

        for (int step = 0; step < 4; ++step){
            for (int s = 0; s < 4; ++s){
                if (tid == 0){ issue(0); issue(1); }

                // ---- stage 1: h = bf16(relu(pe @ W1^T + b1) * sf); warp w -> rows 4w..4w+3
                #pragma unroll
                for (int cc = 0; cc < 4; ++cc){
                    int c4 = cc*128 + lane*4;
                    float4 wx = *reinterpret_cast<const float4*>(&w1xs[c4]);
                    float4 wy = *reinterpret_cast<const float4*>(&w1ys[c4]);
                    float4 wz = *reinterpret_cast<const float4*>(&w1zs[c4]);
                    float4 bb = *reinterpret_cast<const float4*>(&b1s[c4]);
                    float4 sf4 = *reinterpret_cast<const float4*>(&sfs[c4]);
                    #pragma unroll
                    for (int rr = 0; rr < 4; ++rr){
                        int r = wid*4 + rr;
                        float px = pe[r][0], py = pe[r][1], pz = pe[r][2];
                        float ox = fmaxf(fmaf(px, wx.x, fmaf(py, wy.x, fmaf(pz, wz.x, bb.x))), 0.f) * sf4.x;
                        float oy = fmaxf(fmaf(px, wx.y, fmaf(py, wy.y, fmaf(pz, wz.y, bb.y))), 0.f) * sf4.y;
                        float oz = fmaxf(fmaf(px, wx.z, fmaf(py, wy.z, fmaf(pz, wz.z, bb.z))), 0.f) * sf4.z;
                        float ow = fmaxf(fmaf(px, wx.w, fmaf(py, wy.w, fmaf(pz, wz.w, bb.w))), 0.f) * sf4.w;
                        __nv_bfloat162 pA = __floats2bfloat162_rn(ox, oy);
                        __nv_bfloat162 pB = __floats2bfloat162_rn(oz, ow);
                        uint2 pk = make_uint2(*reinterpret_cast<uint32_t*>(&pA),
                                              *reinterpret_cast<uint32_t*>(&pB));
                        *reinterpret_cast<uint2*>(&hb2[r*(HBS/2) + (c4 >> 1)]) = pk;
                    }
                }
                __syncthreads();   // h published before A-frag reads

                // ================= GEMM 1 (W2): h = relu(h@W2^T + b2) + h =================
                {
                    float acc[2][8][4];
                    #pragma unroll
                    for (int m = 0; m < 2; ++m)
                        #pragma unroll
                        for (int j = 0; j < 8; ++j)
                            #pragma unroll
                            for (int q = 0; q < 4; ++q) acc[m][j][q] = 0.f;

                    #pragma unroll 1
                    for (int c = 0; c < NCH; ++c){
                        if (tid == 0 && c + 2 < 2*NCH) issue(c + 2);
                        uint32_t j = (gb + (uint32_t)c) % NBUF;
                        mbar_wait(mbarF + j*8, (cful >> j) & 1u);
                        cful ^= (1u << j);
                        const uint32_t wcu = wc_u32 + j*CHBYTES;
                        switch (phase){
                            case 0: chunk_mma<0>(acc, hb_u32, wcu, c, rbase, colbase, a_lrow, a_koff, b_lrow, bq); break;
                            case 1: chunk_mma<1>(acc, hb_u32, wcu, c, rbase, colbase, a_lrow, a_koff, b_lrow, bq); break;
                            case 2: chunk_mma<2>(acc, hb_u32, wcu, c, rbase, colbase, a_lrow, a_koff, b_lrow, bq); break;
                            default: chunk_mma<3>(acc, hb_u32, wcu, c, rbase, colbase, a_lrow, a_koff, b_lrow, bq); break;
                        }
                        if (lane == 0) MBAR_ARRIVE(mbarE + j*8);
                    }
                    __syncthreads();   // all warps done reading hb before rewrite

                    #pragma unroll
                    for (int m = 0; m < 2; ++m){
                        int r = rbase + 16*m + g;
                        #pragma unroll
                        for (int j = 0; j < 8; ++j){
                            int cc = colbase + 8*j + 2*tig;
                            float bi0 = b2s[cc], bi1 = b2s[cc+1];
                            #pragma unroll
                            for (int hh = 0; hh < 2; ++hh){
                                uint32_t* hp = &hb2[(r + 8*hh)*(HBS/2) + (cc >> 1)];
                                __nv_bfloat162 old = *reinterpret_cast<__nv_bfloat162*>(hp);
                                float nx = fmaxf(acc[m][j][2*hh]   + bi0, 0.f) + __bfloat162float(old.x);
                                float ny = fmaxf(acc[m][j][2*hh+1] + bi1, 0.f) + __bfloat162float(old.y);
                                __nv_bfloat162 nv = __floats2bfloat162_rn(nx, ny);
                                *hp = *reinterpret_cast<uint32_t*>(&nv);
                            }
                        }
                    }
                    __syncthreads();   // h published for GEMM 2
                }

                // ===== GEMM 2 (W3) + fused stage 4: kcur = tanh((relu(h@W3+b3)+h) @ W4^T + b4) =====
                {
                    float acc[2][8][4];
                    #pragma unroll
                    for (int m = 0; m < 2; ++m)
                        #pragma unroll
                        for (int j = 0; j < 8; ++j)
                            #pragma unroll
                            for (int q = 0; q < 4; ++q) acc[m][j][q] = 0.f;

                    #pragma unroll 1
                    for (int c = 0; c < NCH; ++c){
                        const int t = NCH + c;
                        if (tid == 0 && t + 2 < 2*NCH) issue(t + 2);
                        uint32_t j = (gb + (uint32_t)t) % NBUF;
                        mbar_wait(mbarF + j*8, (cful >> j) & 1u);
                        cful ^= (1u << j);
                        const uint32_t wcu = wc_u32 + j*CHBYTES;
                        switch (phase){
                            case 0: chunk_mma<0>(acc, hb_u32, wcu, c, rbase, colbase, a_lrow, a_koff, b_lrow, bq); break;
                            case 1: chunk_mma<1>(acc, hb_u32, wcu, c, rbase, colbase, a_lrow, a_koff, b_lrow, bq); break;
                            case 2: chunk_mma<2>(acc, hb_u32, wcu, c, rbase, colbase, a_lrow, a_koff, b_lrow, bq); break;
                            default: chunk_mma<3>(acc, hb_u32, wcu, c, rbase, colbase, a_lrow, a_koff, b_lrow, bq); break;
                        }
                        if (lane == 0) MBAR_ARRIVE(mbarE + j*8);
                    }
                    // no hb rewrite in this epilogue -> no barrier needed here

                    // fused epilogue: h3 in fp32 regs, partial W4 dots
                    float kp[2][2][3];
                    #pragma unroll
                    for (int m = 0; m < 2; ++m)
                        #pragma unroll
                        for (int hh = 0; hh < 2; ++hh){
                            kp[m][hh][0] = 0.f; kp[m][hh][1] = 0.f; kp[m][hh][2] = 0.f;
                        }
                    #pragma unroll
                    for (int m = 0; m < 2; ++m){
                        int r = rbase + 16*m + g;
                        #pragma unroll
                        for (int j = 0; j < 8; ++j){
                            int cc = colbase + 8*j + 2*tig;
                            float bi0 = b3s[cc], bi1 = b3s[cc+1];
                            float w40 = w4s[cc],        w41 = w4s[cc+1];
                            float w50 = w4s[512+cc],    w51 = w4s[512+cc+1];
                            float w60 = w4s[1024+cc],   w61 = w4s[1024+cc+1];
                            #pragma unroll
                            for (int hh = 0; hh < 2; ++hh){
                                uint32_t pv = hb2[(r + 8*hh)*(HBS/2) + (cc >> 1)];
                                __nv_bfloat162 old = *reinterpret_cast<__nv_bfloat162*>(&pv);
                                float nx = fmaxf(acc[m][j][2*hh]   + bi0, 0.f) + __bfloat162float(old.x);
                                float ny = fmaxf(acc[m][j][2*hh+1] + bi1, 0.f) + __bfloat162float(old.y);
                                kp[m][hh][0] = fmaf(nx, w40, fmaf(ny, w41, kp[m][hh][0]));
                                kp[m][hh][1] = fmaf(nx, w50, fmaf(ny, w51, kp[m][hh][1]));
                                kp[m][hh][2] = fmaf(nx, w60, fmaf(ny, w61, kp[m][hh][2]));
                            }
                        }
                    }
                    // reduce across tig (lanes 0..3 within each g)
                    #pragma unroll
                    for (int m = 0; m < 2; ++m)
                        #pragma unroll
                        for (int hh = 0; hh < 2; ++hh)
                            #pragma unroll
                            for (int d = 0; d < 3; ++d){
                                float v = kp[m][hh][d];
                                v += __shfl_xor_sync(0xffffffffu, v, 1);
                                v += __shfl_xor_sync(0xffffffffu, v, 2);
                                if (tig == 0) kpart[rbase + 16*m + g + 8*hh][cw][d] = v;
                            }
                    __syncthreads();
                    if (tid < ROWS*3){
                        int r = tid/3, d = tid - r*3;
                        float v = kpart[r][0][d];
                        #pragma unroll
                        for (int i = 1; i < 8; ++i) v += kpart[r][i][d];
                        kcur[r][d] = tanhf(v + B4[d]);
                    }
                    __syncthreads();
                }
                gb += 2*NCH;

                // ---- RK4 state update
                if (tid < ROWS*3){
                    int r = tid/3, j = tid - r*3;
                    float k = kcur[r][j];
                    if (s == 0){ ksum[r][j] = k;            pe[r][j] = fmaf(0.5f*dt, k, p0[r][j]); }
                    else if (s == 1){ ksum[r][j] += 2.f*k;  pe[r][j] = fmaf(0.5f*dt, k, p0[r][j]); }
                    else if (s == 2){ ksum[r][j] += 2.f*k;  pe[r][j] = fmaf(dt, k, p0[r][j]); }
                    else { float p = fmaf(dt/6.f, ksum[r][j] + k, p0[r][j]); p0[r][j] = p; pe[r][j] = p; }
                }
                __syncthreads();
            }
        }
    }

    if (tid < ROWS*3){
        int r = tid/3, j = tid - r*3;
        x_out[(base + r)*3 + j] = p0[r][j];
    }
    __syncthreads();
    if (tid == 0){
        #pragma unroll
        for (int j = 0; j < NBUF; ++j){ MBAR_INVAL(mbarF + j*8); MBAR_INVAL(mbarE + j*8); }
    }
}

extern "C" void kernel_launch(void* const* d_in, const int* in_sizes, int n_in,
                              void* d_out, int out_size)
{
    const float* code   = (const float*)d_in[0];
    const float* x      = (const float*)d_in[1];
    const float* f1_l1w = (const float*)d_in[2];
    const float* f1_l1b = (const float*)d_in[3];
    const float* f1_l2w = (const float*)d_in[4];
    const float* f1_l2b = (const float*)d_in[5];
    const float* f1_l3w = (const float*)d_in[6];
    const float* f1_l3b = (const float*)d_in[7];
    const float* f1_l4w = (const float*)d_in[8];
    const float* f1_l4b = (const float*)d_in[9];
    const float* f1_cw  = (const float*)d_in[10];
    const float* f1_cb  = (const float*)d_in[11];
    const float* f2_l1w = (const float*)d_in[12];
    const float* f2_l1b = (const float*)d_in[13];
    const float* f2_l2w = (const float*)d_in[14];
    const float* f2_l2b = (const float*)d_in[15];
    const float* f2_l3w = (const float*)d_in[16];
    const float* f2_l3b = (const float*)d_in[17];
    const float* f2_l4w = (const float*)d_in[18];
    const float* f2_l4b = (const float*)d_in[19];
    const float* f2_cw  = (const float*)d_in[20];
    const float* f2_cb  = (const float*)d_in[21];
    float* out = (float*)d_out;

    const int smem_bytes = 1024 + ROWS*HBS*2 + NBUF*CHBYTES + 5120*4;   // ~182 KB dynamic
    cudaFuncSetAttribute(deform_kernel, cudaFuncAttributeMaxDynamicSharedMemorySize, smem_bytes);

    prep_w<<<dim3(NCH, 4), NT>>>(f1_l2w, f1_l3w, f2_l2w, f2_l3w);
    sf_kernel<<<dim3(4, 2), HDIM>>>(code, f1_cw, f1_cb, f2_cw, f2_cb);

    const int n_blocks = (4 * 4096) / ROWS;  // 256
    deform_kernel<<<n_blocks, NT, smem_bytes>>>(
        x, out,
        f1_l1w, f1_l1b, f1_l2b, f1_l3b, f1_l4w, f1_l4b,
        f2_l1w, f2_l1b, f2_l2b, f2_l3b, f2_l4w, f2_l4b);
}